// round 3
// baseline (speedup 1.0000x reference)
#include <cuda_runtime.h>
#include <cstddef>

#define Hd   50
#define HP   52      // weight row stride (floats): 208B, 16B-aligned
#define NJ4  13      // 52/4 float4-chunks per row
#define HPH  68      // h/input row stride (floats): 272B == 16 mod 128 -> conflict-free
#define HPH4 17      // 68/4
#define G4   200     // 4*H
#define Bsz  4096
#define Tt   256
#define EPB  16      // batch elements per block
#define EPT  2       // elements per thread
#define NTHR 400     // 50 units * 8 element-groups

typedef unsigned long long ull;

// Ping-pong inter-layer activations: [T][B][H] fp32
__device__ float g_ysA[(size_t)Tt * Bsz * Hd];
__device__ float g_ysB[(size_t)Tt * Bsz * Hd];

__device__ __forceinline__ ull ffma2(ull a, ull b, ull c) {
    ull d;
    asm("fma.rn.f32x2 %0, %1, %2, %3;" : "=l"(d) : "l"(a), "l"(b), "l"(c));
    return d;
}
__device__ __forceinline__ float f2sum(ull v) {
    float lo, hi;
    asm("mov.b64 {%0, %1}, %2;" : "=f"(lo), "=f"(hi) : "l"(v));
    return lo + hi;
}
__device__ __forceinline__ float sigf(float x) {
    return __fdividef(1.0f, 1.0f + __expf(-x));
}
__device__ __forceinline__ float tanhf_fast(float x) {
    return 1.0f - __fdividef(2.0f, __expf(2.0f * x) + 1.0f);
}

// One LSTM layer over the full sequence for a tile of EPB batch elements.
// Thread mapping: u = tid>>3 (hidden unit), eg = tid&7 (element group of 2).
__global__ __launch_bounds__(NTHR, 2)
void lstm_layer_kernel(const float* __restrict__ x,
                       const float* __restrict__ ys_in,
                       const float* __restrict__ w_ih,
                       const float* __restrict__ w_hh,
                       const float* __restrict__ bias,
                       float* __restrict__ ys_out,
                       const float* __restrict__ fc_w,
                       const float* __restrict__ fc_b,
                       float* __restrict__ out,
                       int layer0)
{
    extern __shared__ float sm[];
    float* Wh  = sm;                    // [200][HP]
    float* Wi  = Wh + G4 * HP;          // [200][HP] (unused for layer0)
    float* hb0 = Wi + G4 * HP;          // [16][HPH] h ping
    float* hb1 = hb0 + EPB * HPH;       // [16][HPH] h pong
    float* ib0 = hb1 + EPB * HPH;       // [16][HPH] input ping
    float* ib1 = ib0 + EPB * HPH;       // [16][HPH] input pong

    const int tid   = threadIdx.x;
    const int e0    = blockIdx.x * EPB;
    const int u     = tid >> 3;
    const int eg    = tid & 7;
    const int ebase = eg * EPT;

    // ---- zero weight pads + state buffers ----
    for (int idx = tid; idx < G4 * HP; idx += NTHR) { Wh[idx] = 0.0f; Wi[idx] = 0.0f; }
    for (int idx = tid; idx < EPB * HPH; idx += NTHR) {
        hb0[idx] = 0.0f; hb1[idx] = 0.0f; ib0[idx] = 0.0f; ib1[idx] = 0.0f;
    }
    __syncthreads();

    // ---- load weights into smem (once per pass) ----
    for (int idx = tid; idx < G4 * Hd; idx += NTHR) {
        int g = idx / Hd, j = idx - g * Hd;
        Wh[g * HP + j] = w_hh[idx];
        if (!layer0) Wi[g * HP + j] = w_ih[idx];
    }

    // Coalesced staging offsets: 2 (e,j) slots per thread (EPB*Hd = 800 = 2*NTHR).
    int soff[2], goff[2];
    #pragma unroll
    for (int k = 0; k < 2; k++) {
        int idx = tid + k * NTHR;
        int e = idx / Hd, j = idx - e * Hd;
        soff[k] = e * HPH + j;
        goff[k] = idx;
    }

    const float bi = bias[u], bf = bias[50 + u], bg = bias[100 + u], bo = bias[150 + u];
    float wx_i = 0.f, wx_f = 0.f, wx_g = 0.f, wx_o = 0.f;
    if (layer0) { wx_i = w_ih[u]; wx_f = w_ih[50 + u]; wx_g = w_ih[100 + u]; wx_o = w_ih[150 + u]; }

    const ulonglong2* Whi = (const ulonglong2*)(Wh + (u)       * HP);
    const ulonglong2* Whf = (const ulonglong2*)(Wh + (50 + u)  * HP);
    const ulonglong2* Whg = (const ulonglong2*)(Wh + (100 + u) * HP);
    const ulonglong2* Who = (const ulonglong2*)(Wh + (150 + u) * HP);
    const ulonglong2* Wii = (const ulonglong2*)(Wi + (u)       * HP);
    const ulonglong2* Wif = (const ulonglong2*)(Wi + (50 + u)  * HP);
    const ulonglong2* Wig = (const ulonglong2*)(Wi + (100 + u) * HP);
    const ulonglong2* Wio = (const ulonglong2*)(Wi + (150 + u) * HP);

    float c0 = 0.0f, c1 = 0.0f;

    __syncthreads();

    for (int t = 0; t < Tt; t++) {
        float* hP = (t & 1) ? hb1 : hb0;   // h(t-1)
        float* hQ = (t & 1) ? hb0 : hb1;   // h(t) target
        float* iP = (t & 1) ? ib1 : ib0;   // input(t) staging

        // ---- stage input for this timestep (coalesced) ----
        if (layer0) {
            if (tid < EPB) iP[tid * HPH] = x[(size_t)(e0 + tid) * Tt + t];
        } else {
            const float* src = ys_in + ((size_t)t * Bsz + e0) * Hd;
            iP[soff[0]] = src[goff[0]];
            iP[soff[1]] = src[goff[1]];
        }
        __syncthreads();   // h(t-1) writes + input(t) staging visible

        const ulonglong2* H4 = (const ulonglong2*)hP;
        const ulonglong2* I4 = (const ulonglong2*)iP;
        const int r0 = (ebase + 0) * HPH4, r1 = (ebase + 1) * HPH4;

        ull ai0 = 0, ai1 = 0, af0 = 0, af1 = 0, ag0 = 0, ag1 = 0, ao0 = 0, ao1 = 0;

        // ---- recurrent dot: h(t-1) @ W_hh^T (LDS.128 + packed f32x2) ----
        #pragma unroll
        for (int q = 0; q < NJ4; q++) {
            ulonglong2 wi = Whi[q], wf = Whf[q], wg = Whg[q], wo = Who[q];
            ulonglong2 h0 = H4[r0 + q], h1 = H4[r1 + q];
            ai0 = ffma2(wi.x, h0.x, ai0); ai0 = ffma2(wi.y, h0.y, ai0);
            ai1 = ffma2(wi.x, h1.x, ai1); ai1 = ffma2(wi.y, h1.y, ai1);
            af0 = ffma2(wf.x, h0.x, af0); af0 = ffma2(wf.y, h0.y, af0);
            af1 = ffma2(wf.x, h1.x, af1); af1 = ffma2(wf.y, h1.y, af1);
            ag0 = ffma2(wg.x, h0.x, ag0); ag0 = ffma2(wg.y, h0.y, ag0);
            ag1 = ffma2(wg.x, h1.x, ag1); ag1 = ffma2(wg.y, h1.y, ag1);
            ao0 = ffma2(wo.x, h0.x, ao0); ao0 = ffma2(wo.y, h0.y, ao0);
            ao1 = ffma2(wo.x, h1.x, ao1); ao1 = ffma2(wo.y, h1.y, ao1);
        }

        // ---- input dot (layers 1..4) ----
        if (!layer0) {
            #pragma unroll
            for (int q = 0; q < NJ4; q++) {
                ulonglong2 wi = Wii[q], wf = Wif[q], wg = Wig[q], wo = Wio[q];
                ulonglong2 x0 = I4[r0 + q], x1 = I4[r1 + q];
                ai0 = ffma2(wi.x, x0.x, ai0); ai0 = ffma2(wi.y, x0.y, ai0);
                ai1 = ffma2(wi.x, x1.x, ai1); ai1 = ffma2(wi.y, x1.y, ai1);
                af0 = ffma2(wf.x, x0.x, af0); af0 = ffma2(wf.y, x0.y, af0);
                af1 = ffma2(wf.x, x1.x, af1); af1 = ffma2(wf.y, x1.y, af1);
                ag0 = ffma2(wg.x, x0.x, ag0); ag0 = ffma2(wg.y, x0.y, ag0);
                ag1 = ffma2(wg.x, x1.x, ag1); ag1 = ffma2(wg.y, x1.y, ag1);
                ao0 = ffma2(wo.x, x0.x, ao0); ao0 = ffma2(wo.y, x0.y, ao0);
                ao1 = ffma2(wo.x, x1.x, ao1); ao1 = ffma2(wo.y, x1.y, ao1);
            }
        }

        // ---- coalesced write-out of h(t-1) (stable this step) ----
        if (ys_out != nullptr && t > 0) {
            float* dst = ys_out + ((size_t)(t - 1) * Bsz + e0) * Hd;
            dst[goff[0]] = hP[soff[0]];
            dst[goff[1]] = hP[soff[1]];
        }

        // ---- gate nonlinearities + state update ----
        float pi0 = f2sum(ai0) + bi, pi1 = f2sum(ai1) + bi;
        float pf0 = f2sum(af0) + bf, pf1 = f2sum(af1) + bf;
        float pg0 = f2sum(ag0) + bg, pg1 = f2sum(ag1) + bg;
        float po0 = f2sum(ao0) + bo, po1 = f2sum(ao1) + bo;
        if (layer0) {
            float xv0 = iP[(ebase + 0) * HPH];
            float xv1 = iP[(ebase + 1) * HPH];
            pi0 += wx_i * xv0; pf0 += wx_f * xv0; pg0 += wx_g * xv0; po0 += wx_o * xv0;
            pi1 += wx_i * xv1; pf1 += wx_f * xv1; pg1 += wx_g * xv1; po1 += wx_o * xv1;
        }
        c0 = sigf(pf0) * c0 + sigf(pi0) * tanhf_fast(pg0);
        c1 = sigf(pf1) * c1 + sigf(pi1) * tanhf_fast(pg1);
        hQ[(ebase + 0) * HPH + u] = sigf(po0) * tanhf_fast(c0);
        hQ[(ebase + 1) * HPH + u] = sigf(po1) * tanhf_fast(c1);
        // no second sync: next iteration's loop-top sync covers hQ writes
    }

    __syncthreads();
    float* hfin = (Tt & 1) ? hb1 : hb0;  // buffer written at t = Tt-1

    if (ys_out != nullptr) {
        float* dst = ys_out + ((size_t)(Tt - 1) * Bsz + e0) * Hd;
        dst[goff[0]] = hfin[soff[0]];
        dst[goff[1]] = hfin[soff[1]];
    }
    if (out != nullptr && tid < EPB) {
        float s = fc_b[0];
        #pragma unroll 10
        for (int j = 0; j < Hd; j++) s += hfin[tid * HPH + j] * fc_w[j];
        out[e0 + tid] = s;
    }
}

extern "C" void kernel_launch(void* const* d_in, const int* in_sizes, int n_in,
                              void* d_out, int out_size)
{
    const float* x     = (const float*)d_in[0];  // [B,T,1]
    const float* w_ih0 = (const float*)d_in[1];  // [200,1]
    const float* w_hh0 = (const float*)d_in[2];  // [200,50]
    const float* b0    = (const float*)d_in[3];  // [200]
    const float* w_ih  = (const float*)d_in[4];  // [4,200,50]
    const float* w_hh  = (const float*)d_in[5];  // [4,200,50]
    const float* b     = (const float*)d_in[6];  // [4,200]
    const float* fc_w  = (const float*)d_in[7];  // [1,50]
    const float* fc_b  = (const float*)d_in[8];  // [1]
    float* out = (float*)d_out;

    float *ysA = nullptr, *ysB = nullptr;
    cudaGetSymbolAddress((void**)&ysA, g_ysA);
    cudaGetSymbolAddress((void**)&ysB, g_ysB);

    const int smem = (2 * G4 * HP + 4 * EPB * HPH) * (int)sizeof(float);
    cudaFuncSetAttribute(lstm_layer_kernel,
                         cudaFuncAttributeMaxDynamicSharedMemorySize, smem);

    const dim3 grid(Bsz / EPB);   // 256 blocks
    const dim3 block(NTHR);       // 400 threads

    // Layer 0: input x (Din=1) -> ysA
    lstm_layer_kernel<<<grid, block, smem>>>(
        x, nullptr, w_ih0, w_hh0, b0, ysA, nullptr, nullptr, nullptr, 1);

    // Layers 1..3: ping-pong ysA/ysB
    const float* src = ysA;
    float* dst = ysB;
    for (int l = 0; l < 3; l++) {
        lstm_layer_kernel<<<grid, block, smem>>>(
            nullptr, src, w_ih + (size_t)l * G4 * Hd, w_hh + (size_t)l * G4 * Hd,
            b + (size_t)l * G4, dst, nullptr, nullptr, nullptr, 0);
        const float* tmp = dst; dst = (float*)src; src = tmp;
    }

    // Layer 4: no ys_out, fused FC head -> out
    lstm_layer_kernel<<<grid, block, smem>>>(
        nullptr, src, w_ih + (size_t)3 * G4 * Hd, w_hh + (size_t)3 * G4 * Hd,
        b + (size_t)3 * G4, nullptr, fc_w, fc_b, out, 0);
}

// round 4
// speedup vs baseline: 1.3083x; 1.3083x over previous
#include <cuda_runtime.h>
#include <cstddef>

#define Hd    50
#define WP    52          // padded row length (floats): 208B = 13*16B
#define G4    200         // 4*H
#define Bsz   4096
#define Tt    256
#define EPW   4           // batch elements per warp
#define WARPS 8
#define NTHR  256
#define EPC   (EPW*WARPS) // 32 elements per CTA
#define NCTA  (Bsz/EPC)   // 128 CTAs

// per-warp smem buffer layout (floats)
#define XB 0              // x-buf  [4][WP]
#define HB (4*WP)         // h-buf  [4][WP]
#define CB (8*WP)         // c-buf  [4][WP]
#define PB (12*WP)        // preact [4][4][WP]  (e, gate, unit)
#define BUFSZ (28*WP)     // 1456 floats per warp

typedef unsigned long long ull;

// Ping-pong inter-layer activations: [T][B][H] fp32
__device__ float g_ysA[(size_t)Tt * Bsz * Hd];
__device__ float g_ysB[(size_t)Tt * Bsz * Hd];

__device__ __forceinline__ ull ffma2(ull a, ull b, ull c) {
    ull d;
    asm("fma.rn.f32x2 %0, %1, %2, %3;" : "=l"(d) : "l"(a), "l"(b), "l"(c));
    return d;
}
__device__ __forceinline__ float f2sum(ull v) {
    float lo, hi;
    asm("mov.b64 {%0, %1}, %2;" : "=f"(lo), "=f"(hi) : "l"(v));
    return lo + hi;
}
__device__ __forceinline__ float sigf(float x) {
    return __fdividef(1.0f, 1.0f + __expf(-x));
}
__device__ __forceinline__ float tanhf_fast(float x) {
    return 1.0f - __fdividef(2.0f, __expf(2.0f * x) + 1.0f);
}

// Warp-autonomous LSTM layer: each warp owns EPW batch elements for the whole
// sequence. Lane = s*4 + e: s in [0,8) owns gate-rows [25s, 25s+25); e in [0,4).
// NO __syncthreads inside the timestep loop — only warp-local __syncwarp.
__global__ __launch_bounds__(NTHR, 1)
void lstm_layer_kernel(const float* __restrict__ x,
                       const float* __restrict__ ys_in,
                       const float* __restrict__ w_ih,
                       const float* __restrict__ w_hh,
                       const float* __restrict__ bias,
                       float* __restrict__ ys_out,
                       const float* __restrict__ fc_w,
                       const float* __restrict__ fc_b,
                       float* __restrict__ out,
                       int layer0)
{
    extern __shared__ float sm[];
    float* Wh   = sm;                 // [200][WP]
    float* Wi   = Wh + G4 * WP;       // [200][WP] (col 0 holds w_ih0 for layer0)
    float* bia  = Wi + G4 * WP;       // [208]
    float* wbuf = bia + 208;          // [WARPS][BUFSZ]

    const int tid  = threadIdx.x;
    const int wid  = tid >> 5;
    const int lane = tid & 31;
    const int s    = lane >> 2;       // row-slot 0..7
    const int e    = lane & 3;        // element 0..3
    const int row0 = 25 * s;
    const int g    = s >> 1;          // gate of this slot
    const int u0   = (s & 1) * 25;    // unit offset of this slot

    float* wb = wbuf + wid * BUFSZ;
    const int b0 = blockIdx.x * EPC + wid * EPW;   // warp's first batch element

    // ---- load weights into smem (zero pads) ----
    for (int i = tid; i < G4 * WP; i += NTHR) {
        int r = i / WP, j = i - r * WP;
        Wh[i] = (j < Hd) ? w_hh[r * Hd + j] : 0.0f;
        float wiv = 0.0f;
        if (!layer0) { if (j < Hd) wiv = w_ih[r * Hd + j]; }
        else         { if (j == 0) wiv = w_ih[r]; }
        Wi[i] = wiv;
    }
    for (int i = tid; i < G4; i += NTHR) bia[i] = bias[i];
    // ---- init this warp's buffers ----
    for (int i = lane; i < BUFSZ; i += 32) wb[i] = 0.0f;
    __syncthreads();   // weights visible to all warps (only CTA barrier, once)

    // ---- prefetch input for t=0 ----
    float xr[7];
    float x0r = 0.0f;
    if (layer0) {
        x0r = x[(size_t)(b0 + e) * Tt + 0];
    } else {
        const float* src = ys_in + (size_t)b0 * Hd;
        #pragma unroll
        for (int k = 0; k < 7; k++) {
            int idx = lane + 32 * k;
            xr[k] = (idx < EPW * Hd) ? src[idx] : 0.0f;
        }
    }

    for (int t = 0; t < Tt; t++) {
        // ---- stage x(t) from prefetch regs into x-buf ----
        float xcur = 0.0f;
        if (layer0) {
            xcur = x0r;
        } else {
            #pragma unroll
            for (int k = 0; k < 7; k++) {
                int idx = lane + 32 * k;
                if (idx < EPW * Hd) {
                    int ee = idx / Hd, jj = idx - ee * Hd;
                    wb[XB + ee * WP + jj] = xr[k];
                }
            }
        }
        // ---- prefetch x(t+1) (latency hidden under the dot phase) ----
        {
            int tn = (t + 1 < Tt) ? t + 1 : t;
            if (layer0) {
                x0r = x[(size_t)(b0 + e) * Tt + tn];
            } else {
                const float* src = ys_in + ((size_t)tn * Bsz + b0) * Hd;
                #pragma unroll
                for (int k = 0; k < 7; k++) {
                    int idx = lane + 32 * k;
                    xr[k] = (idx < EPW * Hd) ? src[idx] : 0.0f;
                }
            }
        }
        __syncwarp();

        ull acc[25];
        // ---- pass 1: recurrent dot (h in registers, weights multicast) ----
        {
            ulonglong2 h2[13];
            const ulonglong2* hp = (const ulonglong2*)(wb + HB + e * WP);
            #pragma unroll
            for (int q = 0; q < 13; q++) h2[q] = hp[q];
            #pragma unroll
            for (int r = 0; r < 25; r++) {
                const ulonglong2* w = (const ulonglong2*)(Wh + (row0 + r) * WP);
                ull a = 0ull;
                #pragma unroll
                for (int q = 0; q < 13; q++) {
                    ulonglong2 wv = w[q];
                    a = ffma2(wv.x, h2[q].x, a);
                    a = ffma2(wv.y, h2[q].y, a);
                }
                acc[r] = a;
            }
        }
        // ---- pass 2: input dot (layers 1..4) ----
        if (!layer0) {
            ulonglong2 x2[13];
            const ulonglong2* xp = (const ulonglong2*)(wb + XB + e * WP);
            #pragma unroll
            for (int q = 0; q < 13; q++) x2[q] = xp[q];
            #pragma unroll
            for (int r = 0; r < 25; r++) {
                const ulonglong2* w = (const ulonglong2*)(Wi + (row0 + r) * WP);
                ull a = acc[r];
                #pragma unroll
                for (int q = 0; q < 13; q++) {
                    ulonglong2 wv = w[q];
                    a = ffma2(wv.x, x2[q].x, a);
                    a = ffma2(wv.y, x2[q].y, a);
                }
                acc[r] = a;
            }
        }
        // ---- finalize preactivations -> preact buf ----
        #pragma unroll
        for (int r = 0; r < 25; r++) {
            int row = row0 + r;
            float p = f2sum(acc[r]) + bia[row];
            if (layer0) p += Wi[row * WP] * xcur;   // rank-1 input dot
            wb[PB + (e * 4 + g) * WP + u0 + r] = p;
        }
        __syncwarp();

        // ---- pointwise gates + state update (200 items over 32 lanes) ----
        #pragma unroll
        for (int k = 0; k < 7; k++) {
            int item = lane + 32 * k;
            if (item < EPW * Hd) {
                int ee = item / Hd, u = item - ee * Hd;
                float pi = wb[PB + (ee * 4 + 0) * WP + u];
                float pf = wb[PB + (ee * 4 + 1) * WP + u];
                float pg = wb[PB + (ee * 4 + 2) * WP + u];
                float po = wb[PB + (ee * 4 + 3) * WP + u];
                float c  = wb[CB + ee * WP + u];
                c = sigf(pf) * c + sigf(pi) * tanhf_fast(pg);
                wb[CB + ee * WP + u] = c;
                wb[HB + ee * WP + u] = sigf(po) * tanhf_fast(c);
            }
        }
        __syncwarp();

        // ---- coalesced ys(t) write ----
        if (ys_out != nullptr) {
            float* dst = ys_out + ((size_t)t * Bsz + b0) * Hd;
            #pragma unroll
            for (int k = 0; k < 7; k++) {
                int idx = lane + 32 * k;
                if (idx < EPW * Hd) {
                    int ee = idx / Hd, jj = idx - ee * Hd;
                    dst[idx] = wb[HB + ee * WP + jj];
                }
            }
        }
    }

    // ---- FC head on final hidden state (last layer only) ----
    if (out != nullptr && lane < EPW) {
        float sres = fc_b[0];
        #pragma unroll 10
        for (int j = 0; j < Hd; j++) sres += wb[HB + lane * WP + j] * fc_w[j];
        out[b0 + lane] = sres;
    }
}

extern "C" void kernel_launch(void* const* d_in, const int* in_sizes, int n_in,
                              void* d_out, int out_size)
{
    const float* x     = (const float*)d_in[0];  // [B,T,1]
    const float* w_ih0 = (const float*)d_in[1];  // [200,1]
    const float* w_hh0 = (const float*)d_in[2];  // [200,50]
    const float* b0    = (const float*)d_in[3];  // [200]
    const float* w_ih  = (const float*)d_in[4];  // [4,200,50]
    const float* w_hh  = (const float*)d_in[5];  // [4,200,50]
    const float* b     = (const float*)d_in[6];  // [4,200]
    const float* fc_w  = (const float*)d_in[7];  // [1,50]
    const float* fc_b  = (const float*)d_in[8];  // [1]
    float* out = (float*)d_out;

    float *ysA = nullptr, *ysB = nullptr;
    cudaGetSymbolAddress((void**)&ysA, g_ysA);
    cudaGetSymbolAddress((void**)&ysB, g_ysB);

    const int smem = (2 * G4 * WP + 208 + WARPS * BUFSZ) * (int)sizeof(float);
    cudaFuncSetAttribute(lstm_layer_kernel,
                         cudaFuncAttributeMaxDynamicSharedMemorySize, smem);

    const dim3 grid(NCTA);    // 128 CTAs, 1/SM
    const dim3 block(NTHR);   // 256 threads = 8 warps

    // Layer 0: input x (Din=1) -> ysA
    lstm_layer_kernel<<<grid, block, smem>>>(
        x, nullptr, w_ih0, w_hh0, b0, ysA, nullptr, nullptr, nullptr, 1);

    // Layers 1..3: ping-pong ysA/ysB
    const float* src = ysA;
    float* dst = ysB;
    for (int l = 0; l < 3; l++) {
        lstm_layer_kernel<<<grid, block, smem>>>(
            nullptr, src, w_ih + (size_t)l * G4 * Hd, w_hh + (size_t)l * G4 * Hd,
            b + (size_t)l * G4, dst, nullptr, nullptr, nullptr, 0);
        const float* tmp = dst; dst = (float*)src; src = tmp;
    }

    // Layer 4: no ys_out, fused FC head -> out
    lstm_layer_kernel<<<grid, block, smem>>>(
        nullptr, src, w_ih + (size_t)3 * G4 * Hd, w_hh + (size_t)3 * G4 * Hd,
        b + (size_t)3 * G4, nullptr, fc_w, fc_b, out, 0);
}